// round 2
// baseline (speedup 1.0000x reference)
#include <cuda_runtime.h>

#define N 8192
#define D 256
#define NC 10
#define GRID 128
#define ROWS_PER_BLOCK (N / GRID)   // 64

// PAR = COV * 0.5 / BATCH_SIZE = 0.5 / 8192
#define PAR 6.103515625e-05

// Global accumulators (scratch; allocation-free per harness rules).
// g_v[c][t]: sum over all rows with label c of out[row][t]
// g_q[c][t]: sum over all rows with label c of out[row][t]^2
__device__ double g_v[NC][D];
__device__ double g_q[NC][D];

__global__ void zero_kernel() {
    int idx = blockIdx.x * blockDim.x + threadIdx.x;
    if (idx < NC * D) {
        ((double*)g_v)[idx] = 0.0;
        ((double*)g_q)[idx] = 0.0;
    }
}

__global__ __launch_bounds__(D) void accum_kernel(const float* __restrict__ out,
                                                  const int* __restrict__ label) {
    __shared__ float sv[NC][D];
    __shared__ float sq[NC][D];
    int t = threadIdx.x;

    #pragma unroll
    for (int c = 0; c < NC; c++) { sv[c][t] = 0.0f; sq[c][t] = 0.0f; }
    __syncthreads();

    int r0 = blockIdx.x * ROWS_PER_BLOCK;
    #pragma unroll 4
    for (int i = 0; i < ROWS_PER_BLOCK; i++) {
        int r = r0 + i;
        float x = out[r * D + t];
        int   l = label[r];          // uniform across block; L1-broadcast
        sv[l][t] += x;
        sq[l][t] += x * x;
    }
    __syncthreads();

    // Flush block partials to global fp64 accumulators.
    #pragma unroll
    for (int c = 0; c < NC; c++) {
        atomicAdd(&g_v[c][t], (double)sv[c][t]);
        atomicAdd(&g_q[c][t], (double)sq[c][t]);
    }
}

__global__ __launch_bounds__(D) void finish_kernel(const float* __restrict__ out,
                                                   const int* __restrict__ label,
                                                   float* __restrict__ res) {
    __shared__ int cnt[NC];
    __shared__ double red[D];
    int t = threadIdx.x;

    if (t < NC) cnt[t] = 0;
    __syncthreads();
    for (int r = t; r < N; r += D) atomicAdd(&cnt[label[r]], 1);
    __syncthreads();

    int l0 = label[0];
    int lL = label[N - 1];
    // Row excluded from A is row N-1; row excluded from B is row 0.
    double x0 = (double)out[t];                 // row 0, column t
    double xL = (double)out[(N - 1) * D + t];   // row N-1, column t

    double eqpart = 0.0;
    double uA = 0.0, uB = 0.0, qAllA = 0.0, qAllB = 0.0;

    #pragma unroll
    for (int c = 0; c < NC; c++) {
        double v = g_v[c][t];
        double q = g_q[c][t];
        double vA = v - ((lL == c) ? xL : 0.0);
        double vB = v - ((l0 == c) ? x0 : 0.0);
        double qA = q - ((lL == c) ? xL * xL : 0.0);
        double qB = q - ((l0 == c) ? x0 * x0 : 0.0);
        double nA = (double)(cnt[c] - (lL == c));
        double nB = (double)(cnt[c] - (l0 == c));
        // per-column contribution to T_eq = sum_c [ nB*S_A + nA*S_B - 2*vA.vB ]
        eqpart += nB * qA + nA * qB - 2.0 * vA * vB;
        uA += vA; uB += vB; qAllA += qA; qAllB += qB;
    }

    // per-column contribution to T_all = (N-1)*S_A + (N-1)*S_B - 2*uA.uB
    double NA = (double)(N - 1);
    double allpart = NA * qAllA + NA * qAllB - 2.0 * uA * uB;

    red[t] = 2.0 * eqpart - allpart;
    __syncthreads();
    #pragma unroll
    for (int s = D / 2; s > 0; s >>= 1) {
        if (t < s) red[t] += red[t + s];
        __syncthreads();
    }
    if (t == 0) res[0] = (float)(PAR * red[0]);
}

extern "C" void kernel_launch(void* const* d_in, const int* in_sizes, int n_in,
                              void* d_out, int out_size) {
    const float* out   = (const float*)d_in[0];
    const int*   label = (const int*)d_in[1];
    float* res = (float*)d_out;

    zero_kernel<<<(NC * D + 255) / 256, 256>>>();
    accum_kernel<<<GRID, D>>>(out, label);
    finish_kernel<<<1, D>>>(out, label, res);
}

// round 3
// speedup vs baseline: 1.7254x; 1.7254x over previous
#include <cuda_runtime.h>

#define N 8192
#define D 256
#define NC 10
#define GRID 256
#define RPB (N / GRID)   // 32 rows per block

// PAR = COV * 0.5 / BATCH_SIZE = 0.5 / 8192
#define PARF 6.103515625e-05

// Global accumulators. Statically zero-initialized by the CUDA runtime.
// finish_kernel resets them to zero after consuming them, so every
// kernel_launch (first call, capture replays) sees zeros. No zero kernel.
__device__ float g_v[NC][D];   // per-class column sums
__device__ float g_q[NC][D];   // per-class column square-sums
__device__ int   g_cnt[NC];    // per-class row counts

__global__ __launch_bounds__(D) void accum_kernel(const float* __restrict__ out,
                                                  const int* __restrict__ label) {
    // Parity-split buffers: even rows -> [0], odd rows -> [1].
    // Halves the dependent LDS->FADD->STS chain length.
    __shared__ float sv[2][NC][D];
    __shared__ float sq[2][NC][D];
    __shared__ int scnt[NC];
    int t = threadIdx.x;

    #pragma unroll
    for (int c = 0; c < NC; c++) {
        sv[0][c][t] = 0.f; sv[1][c][t] = 0.f;
        sq[0][c][t] = 0.f; sq[1][c][t] = 0.f;
    }
    if (t < NC) scnt[t] = 0;
    __syncthreads();

    int r0 = blockIdx.x * RPB;

    // Count this block's labels (one thread per row).
    if (t < RPB) atomicAdd(&scnt[label[r0 + t]], 1);

    #pragma unroll 8
    for (int i = 0; i < RPB; i++) {
        int r = r0 + i;
        float x = out[(size_t)r * D + t];
        int   l = label[r];            // uniform across block -> L1 broadcast
        int   p = i & 1;
        sv[p][l][t] += x;              // conflict-free: l uniform, t consecutive
        sq[p][l][t] += x * x;
    }
    __syncthreads();

    // Flush block partials (fp32 RED at L2; 20 atomics/thread).
    #pragma unroll
    for (int c = 0; c < NC; c++) {
        atomicAdd(&g_v[c][t], sv[0][c][t] + sv[1][c][t]);
        atomicAdd(&g_q[c][t], sq[0][c][t] + sq[1][c][t]);
    }
    if (t < NC) atomicAdd(&g_cnt[t], scnt[t]);
}

__global__ __launch_bounds__(D) void finish_kernel(const float* __restrict__ out,
                                                   const int* __restrict__ label,
                                                   float* __restrict__ res) {
    __shared__ double red[D];
    __shared__ int cnt[NC];
    int t = threadIdx.x;

    if (t < NC) { cnt[t] = g_cnt[t]; g_cnt[t] = 0; }  // consume + reset
    __syncthreads();

    int l0 = label[0];
    int lL = label[N - 1];
    // Row set A = [0, N-1) excludes row N-1; B = [1, N) excludes row 0.
    float x0 = out[t];                      // row 0, column t
    float xL = out[(size_t)(N - 1) * D + t];

    float eqp = 0.f;          // per-column contribution to T_eq
    float uA = 0.f, uB = 0.f; // column sums over all classes (for T_all)
    float qa = 0.f, qb = 0.f; // column square-sums over all classes

    #pragma unroll
    for (int c = 0; c < NC; c++) {
        float v = g_v[c][t]; g_v[c][t] = 0.f;  // consume + reset
        float q = g_q[c][t]; g_q[c][t] = 0.f;
        float vA = v - ((lL == c) ? xL : 0.f);
        float vB = v - ((l0 == c) ? x0 : 0.f);
        float qA = q - ((lL == c) ? xL * xL : 0.f);
        float qB = q - ((l0 == c) ? x0 * x0 : 0.f);
        float nA = (float)(cnt[c] - (lL == c));
        float nB = (float)(cnt[c] - (l0 == c));
        // T_eq = sum_c [ nB*S_c^A + nA*S_c^B - 2 * vA . vB ]
        eqp += nB * qA + nA * qB - 2.f * vA * vB;
        uA += vA; uB += vB; qa += qA; qb += qB;
    }

    // T_all = (N-1)*(S_A + S_B) - 2 * uA . uB   (per-column slice)
    double allp = (double)(N - 1) * ((double)qa + (double)qb)
                - 2.0 * (double)uA * (double)uB;
    red[t] = 2.0 * (double)eqp - allp;
    __syncthreads();

    #pragma unroll
    for (int s = D / 2; s > 0; s >>= 1) {
        if (t < s) red[t] += red[t + s];
        __syncthreads();
    }
    if (t == 0) res[0] = (float)(PARF * red[0]);
}

extern "C" void kernel_launch(void* const* d_in, const int* in_sizes, int n_in,
                              void* d_out, int out_size) {
    const float* out   = (const float*)d_in[0];
    const int*   label = (const int*)d_in[1];
    float* res = (float*)d_out;

    accum_kernel<<<GRID, D>>>(out, label);
    finish_kernel<<<1, D>>>(out, label, res);
}

// round 4
// speedup vs baseline: 1.9301x; 1.1186x over previous
#include <cuda_runtime.h>

#define N 8192
#define D 256
#define NC 10
#define NP 5              // class pairs (NC/2)
#define GRID 128
#define BLOCK 256
#define RPB (N / GRID)    // 64 rows per block

// PAR = COV * 0.5 / BATCH_SIZE = 0.5 / 8192
#define PARF 6.103515625e-05

// Global accumulators. Statically zero-initialized; the finishing block
// resets them after consuming, so every launch (and graph replay) sees zeros.
// g_pack[p][t] = { v_{2p}[t], q_{2p}[t], v_{2p+1}[t], q_{2p+1}[t] }
__device__ float4 g_pack[NP][D];
__device__ int    g_cnt[NC];
__device__ unsigned int g_done;

__device__ __forceinline__ void red_add_v4(float4* addr, float4 v) {
    asm volatile("red.global.add.v4.f32 [%0], {%1, %2, %3, %4};"
                 :: "l"(addr), "f"(v.x), "f"(v.y), "f"(v.z), "f"(v.w)
                 : "memory");
}

__global__ __launch_bounds__(BLOCK) void fused_kernel(const float* __restrict__ out,
                                                      const int* __restrict__ label,
                                                      float* __restrict__ res) {
    // Parity-split (v,q) accumulators: halves the dependent LDS->FADD->STS chain.
    __shared__ float2 svq[2][NC][D];     // 40 KB
    __shared__ int   s_lab[RPB];
    __shared__ int   scnt[NC];
    __shared__ int   s_last;
    __shared__ double red[BLOCK];

    int t = threadIdx.x;
    int r0 = blockIdx.x * RPB;

    #pragma unroll
    for (int c = 0; c < NC; c++) {
        svq[0][c][t] = make_float2(0.f, 0.f);
        svq[1][c][t] = make_float2(0.f, 0.f);
    }
    if (t < NC) scnt[t] = 0;
    if (t < RPB) s_lab[t] = label[r0 + t];
    __syncthreads();

    if (t < RPB) atomicAdd(&scnt[s_lab[t]], 1);

    // ---- accumulate 64 rows: column t of each row ----
    #pragma unroll 8
    for (int i = 0; i < RPB; i++) {
        float x = out[(size_t)(r0 + i) * D + t];
        int   l = s_lab[i];              // uniform across block
        float2 a = svq[i & 1][l][t];
        a.x += x;
        a.y += x * x;
        svq[i & 1][l][t] = a;
    }
    __syncthreads();

    // ---- flush block partials: 5 vector REDs per thread ----
    #pragma unroll
    for (int p = 0; p < NP; p++) {
        int c0 = 2 * p, c1 = 2 * p + 1;
        float2 a0 = svq[0][c0][t], b0 = svq[1][c0][t];
        float2 a1 = svq[0][c1][t], b1 = svq[1][c1][t];
        red_add_v4(&g_pack[p][t],
                   make_float4(a0.x + b0.x, a0.y + b0.y,
                               a1.x + b1.x, a1.y + b1.y));
    }
    if (t < NC && scnt[t]) atomicAdd(&g_cnt[t], scnt[t]);

    // ---- last-block-arrival handoff ----
    __threadfence();
    __syncthreads();
    if (t == 0) {
        unsigned int prev = atomicAdd(&g_done, 1u);
        s_last = (prev == GRID - 1);
    }
    __syncthreads();
    if (!s_last) return;

    // =================== finish phase (one block) ===================
    __threadfence();   // acquire side of the counter handshake

    __shared__ int cnt[NC];
    if (t < NC) { cnt[t] = g_cnt[t]; g_cnt[t] = 0; }
    if (t == 0) g_done = 0;
    __syncthreads();

    int l0 = label[0];
    int lL = label[N - 1];
    // Row set A = [0, N-1) excludes row N-1; B = [1, N) excludes row 0.
    float x0 = out[t];                        // row 0,   column t
    float xL = out[(size_t)(N - 1) * D + t];  // row N-1, column t

    float eqp = 0.f;           // per-column contribution to T_eq
    float uA = 0.f, uB = 0.f;  // column sums over all classes (for T_all)
    float qa = 0.f, qb = 0.f;  // column square-sums over all classes

    #pragma unroll
    for (int p = 0; p < NP; p++) {
        float4 vq = g_pack[p][t];
        g_pack[p][t] = make_float4(0.f, 0.f, 0.f, 0.f);   // consume + reset
        #pragma unroll
        for (int h = 0; h < 2; h++) {
            int   c = 2 * p + h;
            float v = h ? vq.z : vq.x;
            float q = h ? vq.w : vq.y;
            float vA = v - ((lL == c) ? xL : 0.f);
            float vB = v - ((l0 == c) ? x0 : 0.f);
            float qA = q - ((lL == c) ? xL * xL : 0.f);
            float qB = q - ((l0 == c) ? x0 * x0 : 0.f);
            float nA = (float)(cnt[c] - (lL == c));
            float nB = (float)(cnt[c] - (l0 == c));
            // T_eq = sum_c [ nB*S_c^A + nA*S_c^B - 2 * vA . vB ]
            eqp += nB * qA + nA * qB - 2.f * vA * vB;
            uA += vA; uB += vB; qa += qA; qb += qB;
        }
    }

    // T_all = (N-1)*(S_A + S_B) - 2 * uA . uB   (per-column slice)
    double allp = (double)(N - 1) * ((double)qa + (double)qb)
                - 2.0 * (double)uA * (double)uB;
    red[t] = 2.0 * (double)eqp - allp;
    __syncthreads();

    #pragma unroll
    for (int s = BLOCK / 2; s > 0; s >>= 1) {
        if (t < s) red[t] += red[t + s];
        __syncthreads();
    }
    if (t == 0) res[0] = (float)(PARF * red[0]);
}

extern "C" void kernel_launch(void* const* d_in, const int* in_sizes, int n_in,
                              void* d_out, int out_size) {
    const float* out   = (const float*)d_in[0];
    const int*   label = (const int*)d_in[1];
    fused_kernel<<<GRID, BLOCK>>>(out, label, (float*)d_out);
}